// round 1
// baseline (speedup 1.0000x reference)
#include <cuda_runtime.h>
#include <math.h>

#define CB   256   // batch
#define CN   77    // tokens
#define CD   768   // token dim
#define CK   16    // nodes
#define CDn  768   // node dim
#define CHID 512   // edge hidden
#define CL   2     // gnn layers

// ---------------- scratch (device globals; no allocation allowed) ----------
__device__ float g_Kt[CB * CN * CDn];
__device__ float g_Vt[CB * CN * CDn];
__device__ float g_Q [CK * CDn];
__device__ float g_A [CB * CK * CK];
__device__ float g_Hi[CB * CK * CHID];
__device__ float g_Hj[CB * CK * CHID];
__device__ float g_Mg[CB * CK * CDn];

// ---------------- Q = nq @ Wq + bq  (batch-invariant, tiny) ----------------
// grid: CDn/128 blocks, 128 threads
__global__ void q_kernel(const float* __restrict__ nq, const float* __restrict__ Wq,
                         const float* __restrict__ bq, float* __restrict__ Qout)
{
    int d = blockIdx.x * 128 + threadIdx.x;
    __shared__ float nqs[CK * 128];
    float acc[CK];
#pragma unroll
    for (int k = 0; k < CK; k++) acc[k] = bq[d];
    for (int e0 = 0; e0 < CDn; e0 += 128) {
        for (int idx = threadIdx.x; idx < CK * 128; idx += 128) {
            int k = idx >> 7, e = idx & 127;
            nqs[idx] = nq[k * CDn + e0 + e];
        }
        __syncthreads();
        for (int e = 0; e < 128; e++) {
            float wv = Wq[(size_t)(e0 + e) * CDn + d];
#pragma unroll
            for (int k = 0; k < CK; k++) acc[k] += nqs[k * 128 + e] * wv;
        }
        __syncthreads();
    }
#pragma unroll
    for (int k = 0; k < CK; k++) Qout[k * CDn + d] = acc[k];
}

// ---------------- generic fp32 GEMM: C[M,Nn] = A[M,Kd] @ W[Kd,Nn](ldw) + b --
// requires M%64==0, Nn%64==0, Kd%16==0; 256 threads; 4x4 micro-tile
__global__ void gemm64(const float* __restrict__ A, const float* __restrict__ W,
                       const float* __restrict__ bias, float* __restrict__ C,
                       int M, int Nn, int Kd, int ldw)
{
    __shared__ float As[16][65];
    __shared__ float Ws[16][64];
    int tid  = threadIdx.x;
    int tr   = tid >> 4;          // 0..15
    int tc   = tid & 15;          // 0..15
    int row0 = blockIdx.y * 64;
    int col0 = blockIdx.x * 64;

    int am = tid >> 2;            // 0..63
    int ak = (tid & 3) * 4;       // 0,4,8,12
    int wk = tid >> 4;            // 0..15
    int wn = (tid & 15) * 4;      // 0..60

    float acc[4][4] = {};

    for (int k0 = 0; k0 < Kd; k0 += 16) {
        float4 av = *(const float4*)(A + (size_t)(row0 + am) * Kd + k0 + ak);
        As[ak + 0][am] = av.x; As[ak + 1][am] = av.y;
        As[ak + 2][am] = av.z; As[ak + 3][am] = av.w;
        float4 wv = *(const float4*)(W + (size_t)(k0 + wk) * ldw + col0 + wn);
        *(float4*)&Ws[wk][wn] = wv;
        __syncthreads();
#pragma unroll
        for (int kk = 0; kk < 16; kk++) {
            float a[4], b[4];
#pragma unroll
            for (int i = 0; i < 4; i++) a[i] = As[kk][tr * 4 + i];
#pragma unroll
            for (int j = 0; j < 4; j++) b[j] = Ws[kk][tc * 4 + j];
#pragma unroll
            for (int i = 0; i < 4; i++)
#pragma unroll
                for (int j = 0; j < 4; j++) acc[i][j] += a[i] * b[j];
        }
        __syncthreads();
    }

#pragma unroll
    for (int i = 0; i < 4; i++) {
        int row = row0 + tr * 4 + i;
        int col = col0 + tc * 4;
        float4 o;
        float b0 = bias ? bias[col + 0] : 0.f;
        float b1 = bias ? bias[col + 1] : 0.f;
        float b2 = bias ? bias[col + 2] : 0.f;
        float b3 = bias ? bias[col + 3] : 0.f;
        o.x = acc[i][0] + b0; o.y = acc[i][1] + b1;
        o.z = acc[i][2] + b2; o.w = acc[i][3] + b3;
        *(float4*)(C + (size_t)row * Nn + col) = o;
    }
}

// ---------------- scores + masked softmax over K -> S [B,N,K] --------------
// grid: B*N blocks, 256 threads
__global__ void scores_kernel(const float* __restrict__ Kt, const float* __restrict__ Q,
                              const int* __restrict__ mask, float* __restrict__ S)
{
    int bn = blockIdx.x;
    __shared__ float kt[CDn];
    __shared__ float sk[CK];
    for (int i = threadIdx.x; i < CDn; i += 256)
        kt[i] = Kt[(size_t)bn * CDn + i];
    __syncthreads();
    int w = threadIdx.x >> 5, lane = threadIdx.x & 31;
    for (int k = w; k < CK; k += 8) {
        float acc = 0.f;
        for (int d = lane; d < CDn; d += 32)
            acc += Q[k * CDn + d] * kt[d];
#pragma unroll
        for (int off = 16; off; off >>= 1)
            acc += __shfl_xor_sync(0xffffffffu, acc, off);
        if (lane == 0) sk[k] = acc;
    }
    __syncthreads();
    if (threadIdx.x < 32) {
        int k = lane;
        if (mask[bn] == 0) {
            if (k < CK) S[(size_t)bn * CK + k] = 1.0f / CK;
        } else {
            const float scale = rsqrtf((float)(CDn / 8));
            float v = (k < CK) ? sk[k] * scale : -INFINITY;
            float m = v;
#pragma unroll
            for (int off = 16; off; off >>= 1)
                m = fmaxf(m, __shfl_xor_sync(0xffffffffu, m, off));
            float e = (k < CK) ? __expf(v - m) : 0.f;
            float s = e;
#pragma unroll
            for (int off = 16; off; off >>= 1)
                s += __shfl_xor_sync(0xffffffffu, s, off);
            if (k < CK) S[(size_t)bn * CK + k] = e / s;
        }
    }
}

// ------- V[b,k,d] = sum_n S[b,n,k]*Vt[b,n,d]; then gate-fuse with nq -------
// grid: (CDn/128, B), 256 threads
__global__ void vagg_kernel(const float* __restrict__ S, const float* __restrict__ Vt,
                            const float* __restrict__ nq, const float* __restrict__ fg,
                            float* __restrict__ Vout)
{
    int b = blockIdx.y;
    int d0 = blockIdx.x * 128;
    __shared__ float Ss[CN * CK];
    __shared__ float vts[128];
    for (int i = threadIdx.x; i < CN * CK; i += 256)
        Ss[i] = S[(size_t)b * CN * CK + i];
    int k  = threadIdx.x >> 4;
    int ds = threadIdx.x & 15;
    float acc[8] = {};
    for (int n = 0; n < CN; n++) {
        __syncthreads();
        if (threadIdx.x < 128)
            vts[threadIdx.x] = Vt[((size_t)b * CN + n) * CDn + d0 + threadIdx.x];
        __syncthreads();
        float sv = Ss[n * CK + k];
#pragma unroll
        for (int c = 0; c < 8; c++) acc[c] += sv * vts[ds + 16 * c];
    }
    float g = 1.f / (1.f + __expf(-fg[0]));
#pragma unroll
    for (int c = 0; c < 8; c++) {
        int d = d0 + ds + 16 * c;
        Vout[((size_t)b * CK + k) * CDn + d] = (1.f - g) * acc[c] + g * nq[k * CDn + d];
    }
}

// ---------------- edge reduce: E[b,i,j] = sum_h relu(hi+hj+be1)*We2 + be2 ---
// grid: B blocks, 256 threads, dynamic smem (transposed tiles, conflict-free)
template <bool DO_SOFTMAX>
__global__ void edge_kernel(const float* __restrict__ Hi, const float* __restrict__ Hj,
                            const float* __restrict__ be1, const float* __restrict__ We2,
                            const float* __restrict__ be2, float* __restrict__ out)
{
    extern __shared__ float sm[];
    float* HIs  = sm;                    // [CHID][CK]
    float* HJs  = HIs + CHID * CK;       // [CHID][CK]
    float* be1s = HJs + CHID * CK;       // [CHID]
    float* we2s = be1s + CHID;           // [CHID]
    float* Es   = we2s + CHID;           // [CK*CK]
    int b = blockIdx.x;
    for (int idx = threadIdx.x; idx < CK * CHID; idx += 256) {
        int i = idx / CHID, h = idx % CHID;
        HIs[h * CK + i] = Hi[((size_t)b * CK + i) * CHID + h];
        HJs[h * CK + i] = Hj[((size_t)b * CK + i) * CHID + h];
    }
    for (int idx = threadIdx.x; idx < CHID; idx += 256) {
        be1s[idx] = be1[idx];
        we2s[idx] = We2[idx];
    }
    __syncthreads();
    int i = threadIdx.x >> 4, j = threadIdx.x & 15;
    float acc = be2[0];
#pragma unroll 4
    for (int h = 0; h < CHID; h++) {
        float v = HIs[h * CK + i] + HJs[h * CK + j] + be1s[h];
        acc += fmaxf(v, 0.f) * we2s[h];
    }
    if (!DO_SOFTMAX) {
        out[(size_t)b * CK * CK + i * CK + j] = acc;
    } else {
        Es[i * CK + j] = acc;
        __syncthreads();
        float m = -INFINITY;
#pragma unroll
        for (int jj = 0; jj < CK; jj++) m = fmaxf(m, Es[i * CK + jj]);
        float ssum = 0.f;
#pragma unroll
        for (int jj = 0; jj < CK; jj++) ssum += __expf(Es[i * CK + jj] - m);
        out[(size_t)b * CK * CK + i * CK + j] = __expf(acc - m) / ssum;
    }
}

// ---------------- GNN update: V[b,i,:] += relu(sum_j A[b,i,j]*M[b,j,:]) ----
// grid: (CDn/128, B), 256 threads
__global__ void gnn_update(const float* __restrict__ A, const float* __restrict__ M,
                           float* __restrict__ V)
{
    int b = blockIdx.y;
    int d0 = blockIdx.x * 128;
    __shared__ float As[CK * CK];
    __shared__ float Ms[128];
    for (int idx = threadIdx.x; idx < CK * CK; idx += 256)
        As[idx] = A[(size_t)b * CK * CK + idx];
    int i  = threadIdx.x >> 4;
    int ds = threadIdx.x & 15;
    float acc[8] = {};
    for (int j = 0; j < CK; j++) {
        __syncthreads();
        if (threadIdx.x < 128)
            Ms[threadIdx.x] = M[((size_t)b * CK + j) * CDn + d0 + threadIdx.x];
        __syncthreads();
        float a = As[i * CK + j];
#pragma unroll
        for (int c = 0; c < 8; c++) acc[c] += a * Ms[ds + 16 * c];
    }
#pragma unroll
    for (int c = 0; c < 8; c++) {
        size_t o = ((size_t)b * CK + i) * CDn + d0 + ds + 16 * c;
        V[o] += fmaxf(acc[c], 0.f);
    }
}

// ---------------------------------------------------------------------------
extern "C" void kernel_launch(void* const* d_in, const int* in_sizes, int n_in,
                              void* d_out, int out_size)
{
    const float* w    = (const float*)d_in[0];
    const int*   mask = (const int*)  d_in[1];
    const float* nq   = (const float*)d_in[2];
    const float* Wq   = (const float*)d_in[3];
    const float* bq   = (const float*)d_in[4];
    const float* Wk   = (const float*)d_in[5];
    const float* bk   = (const float*)d_in[6];
    const float* Wv   = (const float*)d_in[7];
    const float* bv   = (const float*)d_in[8];
    const float* We1  = (const float*)d_in[9];
    const float* be1  = (const float*)d_in[10];
    const float* We2  = (const float*)d_in[11];
    const float* be2  = (const float*)d_in[12];
    const float* fg   = (const float*)d_in[13];
    const float* Wg   = (const float*)d_in[14];
    const float* bg   = (const float*)d_in[15];

    float* S = (float*)d_out;                       // [B,N,K]
    float* V = S + (size_t)CB * CN * CK;            // [B,K,Dn]
    float* E = V + (size_t)CB * CK * CDn;           // [B,K,K]

    float *Kt, *Vt, *Qb, *Ab, *Hi, *Hj, *Mg;
    cudaGetSymbolAddress((void**)&Kt, g_Kt);
    cudaGetSymbolAddress((void**)&Vt, g_Vt);
    cudaGetSymbolAddress((void**)&Qb, g_Q);
    cudaGetSymbolAddress((void**)&Ab, g_A);
    cudaGetSymbolAddress((void**)&Hi, g_Hi);
    cudaGetSymbolAddress((void**)&Hj, g_Hj);
    cudaGetSymbolAddress((void**)&Mg, g_Mg);

    const int EDGE_SMEM = (2 * CHID * CK + 2 * CHID + CK * CK) * (int)sizeof(float);
    cudaFuncSetAttribute(edge_kernel<true>,  cudaFuncAttributeMaxDynamicSharedMemorySize, EDGE_SMEM);
    cudaFuncSetAttribute(edge_kernel<false>, cudaFuncAttributeMaxDynamicSharedMemorySize, EDGE_SMEM);

    const int Mtok = CB * CN;   // 19712
    const int Mkv  = CB * CK;   // 4096

    // 1. Q (batch-invariant)
    q_kernel<<<CDn / 128, 128>>>(nq, Wq, bq, Qb);

    // 2. Kt, Vt projections (dominant GEMMs)
    gemm64<<<dim3(CDn / 64, Mtok / 64), 256>>>(w, Wk, bk, Kt, Mtok, CDn, CD, CDn);
    gemm64<<<dim3(CDn / 64, Mtok / 64), 256>>>(w, Wv, bv, Vt, Mtok, CDn, CD, CDn);

    // 3. scores + masked softmax over K -> S
    scores_kernel<<<Mtok, 256>>>(Kt, Qb, mask, S);

    // 4. V aggregation + fuse gate
    vagg_kernel<<<dim3(CDn / 128, CB), 256>>>(S, Vt, nq, fg, V);

    // 5. pre-GNN edge logits -> A = softmax(E)
    gemm64<<<dim3(CHID / 64, Mkv / 64), 256>>>(V, We1,                 nullptr, Hi, Mkv, CHID, CDn, CHID);
    gemm64<<<dim3(CHID / 64, Mkv / 64), 256>>>(V, We1 + CDn * CHID,    nullptr, Hj, Mkv, CHID, CDn, CHID);
    edge_kernel<true><<<CB, 256, EDGE_SMEM>>>(Hi, Hj, be1, We2, be2, Ab);

    // 6. GNN layers
    for (int l = 0; l < CL; l++) {
        gemm64<<<dim3(CDn / 64, Mkv / 64), 256>>>(V, Wg + (size_t)l * CDn * CDn,
                                                  bg + (size_t)l * CDn, Mg, Mkv, CDn, CDn, CDn);
        gnn_update<<<dim3(CDn / 128, CB), 256>>>(Ab, Mg, V);
    }

    // 7. post-GNN edge logits -> E (output)
    gemm64<<<dim3(CHID / 64, Mkv / 64), 256>>>(V, We1,              nullptr, Hi, Mkv, CHID, CDn, CHID);
    gemm64<<<dim3(CHID / 64, Mkv / 64), 256>>>(V, We1 + CDn * CHID, nullptr, Hj, Mkv, CHID, CDn, CHID);
    edge_kernel<false><<<CB, 256, EDGE_SMEM>>>(Hi, Hj, be1, We2, be2, E);
}

// round 3
// speedup vs baseline: 2.2314x; 2.2314x over previous
#include <cuda_runtime.h>
#include <cuda_bf16.h>
#include <math.h>
#include <stdint.h>

#define CB   256   // batch
#define CN   77    // tokens
#define CD   768   // token dim
#define CK   16    // nodes
#define CDn  768   // node dim
#define CHID 512   // edge hidden
#define CL   2     // gnn layers

#define GK     768          // shared inner dim of all GEMMs
#define KCH    64           // bf16 K elems per chunk (128B rows)
#define NCHUNK (GK / KCH)   // 12
#define TILEB  16384        // one 128x64 bf16 tile in smem
#define BUFB   (4 * TILEB)  // Ah, Al, Bh, Bl
#define GSMEM  (2 * BUFB)   // 131072

// ---------------- scratch (device globals; no allocation allowed) ----------
__device__ float g_Kt[CB * CN * CDn];
__device__ float g_Vt[CB * CN * CDn];
__device__ float g_Q [CK * CDn];
__device__ float g_A [CB * CK * CK];
__device__ float g_Hi[CB * CK * CHID];
__device__ float g_Hj[CB * CK * CHID];
__device__ float g_Mg[CB * CK * CDn];
__device__ __nv_bfloat16 g_wh[CB * CN * CDn];
__device__ __nv_bfloat16 g_wl[CB * CN * CDn];
__device__ __nv_bfloat16 g_vh[CB * CK * CDn];
__device__ __nv_bfloat16 g_vl[CB * CK * CDn];
// transposed weights [Nrows, 768]: Wk(0) Wv(768) We1a(1536) We1b(2048) Wg0(2560) Wg1(3328)
__device__ __nv_bfloat16 g_Wth[4096 * GK];
__device__ __nv_bfloat16 g_Wtl[4096 * GK];

// ---------------- PTX helpers ----------------------------------------------
__device__ __forceinline__ uint32_t smem_u32(const void* p) {
    uint32_t a;
    asm("{ .reg .u64 t; cvta.to.shared.u64 t, %1; cvt.u32.u64 %0, t; }" : "=r"(a) : "l"(p));
    return a;
}
__device__ __forceinline__ void cpa16(uint32_t sa, const void* ga) {
    asm volatile("cp.async.cg.shared.global [%0], [%1], 16;" :: "r"(sa), "l"(ga));
}
__device__ __forceinline__ void ldsm4(uint32_t* r, uint32_t addr) {
    asm volatile("ldmatrix.sync.aligned.m8n8.x4.shared.b16 {%0,%1,%2,%3}, [%4];"
                 : "=r"(r[0]), "=r"(r[1]), "=r"(r[2]), "=r"(r[3]) : "r"(addr));
}
__device__ __forceinline__ void mma16816(float* c, const uint32_t* a, uint32_t b0, uint32_t b1) {
    asm volatile(
        "mma.sync.aligned.m16n8k16.row.col.f32.bf16.bf16.f32 "
        "{%0,%1,%2,%3}, {%4,%5,%6,%7}, {%8,%9}, {%0,%1,%2,%3};"
        : "+f"(c[0]), "+f"(c[1]), "+f"(c[2]), "+f"(c[3])
        : "r"(a[0]), "r"(a[1]), "r"(a[2]), "r"(a[3]), "r"(b0), "r"(b1));
}

// ---------------- split/convert kernels -------------------------------------
__global__ void split_rows(const float* __restrict__ x, __nv_bfloat16* __restrict__ hi,
                           __nv_bfloat16* __restrict__ lo, int n4) {
    int i = blockIdx.x * 256 + threadIdx.x;
    if (i >= n4) return;
    float4 v = ((const float4*)x)[i];
    float h0 = __bfloat162float(__float2bfloat16(v.x));
    float h1 = __bfloat162float(__float2bfloat16(v.y));
    float h2 = __bfloat162float(__float2bfloat16(v.z));
    float h3 = __bfloat162float(__float2bfloat16(v.w));
    ((__nv_bfloat162*)hi)[2 * i + 0] = __nv_bfloat162(__float2bfloat16(h0), __float2bfloat16(h1));
    ((__nv_bfloat162*)hi)[2 * i + 1] = __nv_bfloat162(__float2bfloat16(h2), __float2bfloat16(h3));
    ((__nv_bfloat162*)lo)[2 * i + 0] =
        __nv_bfloat162(__float2bfloat16(v.x - h0), __float2bfloat16(v.y - h1));
    ((__nv_bfloat162*)lo)[2 * i + 1] =
        __nv_bfloat162(__float2bfloat16(v.z - h2), __float2bfloat16(v.w - h3));
}

// transpose W[768, ncols](row stride ld) -> dst[ncols, 768] bf16 hi/lo
__global__ void split_transpose(const float* __restrict__ src, int ld,
                                __nv_bfloat16* __restrict__ dh, __nv_bfloat16* __restrict__ dl) {
    __shared__ float t[32][33];
    int n0 = blockIdx.x * 32, k0 = blockIdx.y * 32;
    int tx = threadIdx.x, ty = threadIdx.y;
#pragma unroll
    for (int j = 0; j < 4; j++)
        t[ty + 8 * j][tx] = src[(size_t)(k0 + ty + 8 * j) * ld + n0 + tx];
    __syncthreads();
#pragma unroll
    for (int j = 0; j < 4; j++) {
        float x = t[tx][ty + 8 * j];
        float h = __bfloat162float(__float2bfloat16(x));
        size_t o = (size_t)(n0 + ty + 8 * j) * GK + k0 + tx;
        dh[o] = __float2bfloat16(h);
        dl[o] = __float2bfloat16(x - h);
    }
}

// ---------------- mma.sync split-bf16 GEMM -----------------------------------
// C[M, Nn] = (Ah+Al)[M,768] @ ((Bh+Bl)[Nn,768])^T + bias.  CTA tile 128x128.
__global__ void __launch_bounds__(256, 1) gemm_mma(
    const __nv_bfloat16* __restrict__ Ah, const __nv_bfloat16* __restrict__ Al,
    const __nv_bfloat16* __restrict__ Bh, const __nv_bfloat16* __restrict__ Bl,
    const float* __restrict__ bias, float* __restrict__ C, int Nn)
{
    extern __shared__ char smem[];
    const uint32_t sbase = smem_u32(smem);
    const int tid = threadIdx.x;
    const int lane = tid & 31, wid = tid >> 5;
    const int warp_m = wid >> 2, warp_n = wid & 3;   // 2 x 4 warp grid
    const int row0 = blockIdx.y * 128;
    const int col0 = blockIdx.x * 128;

    // gmem->smem: 4096 16B-chunks per buffer, 16 per thread
    const int lr = (tid >> 3) & 31;      // base row slice helper (unused directly)
    (void)lr;

    float acc[4][4][4];
#pragma unroll
    for (int a = 0; a < 4; a++)
#pragma unroll
        for (int b = 0; b < 4; b++)
#pragma unroll
            for (int c = 0; c < 4; c++) acc[a][b][c] = 0.f;

#define ISSUE_CHUNK(chunk, buf)                                                     \
    do {                                                                            \
        uint32_t bufo_ = sbase + (buf) * BUFB;                                      \
        _Pragma("unroll")                                                           \
        for (int it = 0; it < 16; it++) {                                           \
            int idx_ = it * 256 + tid;                                              \
            int t_ = idx_ >> 10;                                                    \
            int r_ = (idx_ >> 3) & 127;                                             \
            int c_ = idx_ & 7;                                                      \
            const __nv_bfloat16* sp_ =                                              \
                (t_ == 0) ? Ah + (size_t)(row0 + r_) * GK :                         \
                (t_ == 1) ? Al + (size_t)(row0 + r_) * GK :                         \
                (t_ == 2) ? Bh + (size_t)(col0 + r_) * GK :                         \
                            Bl + (size_t)(col0 + r_) * GK;                          \
            sp_ += (chunk) * KCH + c_ * 8;                                          \
            uint32_t sa_ = bufo_ + t_ * TILEB + r_ * 128 + ((c_ ^ (r_ & 7)) << 4);  \
            cpa16(sa_, sp_);                                                        \
        }                                                                           \
        asm volatile("cp.async.commit_group;" ::: "memory");                        \
    } while (0)

    ISSUE_CHUNK(0, 0);

    const int rA  = warp_m * 64 + (lane & 15);   // A row within tile (per mt: +16*mt)
    const int khA = lane >> 4;                   // k half for A ldmatrix
    const int rB  = warp_n * 32 + (lane & 7) + ((lane >> 4) << 3);
    const int khB = (lane >> 3) & 1;
    const int swA = rA & 7, swB = rB & 7;

    for (int i = 0; i < NCHUNK; i++) {
        if (i + 1 < NCHUNK) {
            ISSUE_CHUNK(i + 1, (i + 1) & 1);
            asm volatile("cp.async.wait_group 1;" ::: "memory");
        } else {
            asm volatile("cp.async.wait_group 0;" ::: "memory");
        }
        __syncthreads();
        uint32_t bufo = sbase + (i & 1) * BUFB;
#pragma unroll
        for (int kk = 0; kk < 4; kk++) {
            uint32_t a[2][4][4];   // [hi/lo][mtile][reg]
            uint32_t b[2][2][4];   // [hi/lo][ntile(16)][reg]
            int ckA = kk * 2 + khA;
            int ckB = kk * 2 + khB;
#pragma unroll
            for (int mt = 0; mt < 4; mt++) {
                uint32_t ad = bufo + (rA + mt * 16) * 128 + (((ckA ^ swA)) << 4);
                ldsm4(a[0][mt], ad);                // Ah
                ldsm4(a[1][mt], ad + TILEB);        // Al
            }
#pragma unroll
            for (int nt = 0; nt < 2; nt++) {
                uint32_t bd = bufo + 2 * TILEB + (rB + nt * 16) * 128 + (((ckB ^ swB)) << 4);
                ldsm4(b[0][nt], bd);                // Bh
                ldsm4(b[1][nt], bd + TILEB);        // Bl
            }
#pragma unroll
            for (int mt = 0; mt < 4; mt++)
#pragma unroll
                for (int ng = 0; ng < 4; ng++) {
                    uint32_t b0h = b[0][ng >> 1][(ng & 1) * 2 + 0];
                    uint32_t b1h = b[0][ng >> 1][(ng & 1) * 2 + 1];
                    uint32_t b0l = b[1][ng >> 1][(ng & 1) * 2 + 0];
                    uint32_t b1l = b[1][ng >> 1][(ng & 1) * 2 + 1];
                    mma16816(acc[mt][ng], a[0][mt], b0h, b1h);   // Ah*Bh
                    mma16816(acc[mt][ng], a[0][mt], b0l, b1l);   // Ah*Bl
                    mma16816(acc[mt][ng], a[1][mt], b0h, b1h);   // Al*Bh
                }
        }
        __syncthreads();
    }

    // epilogue
    const int rowE = row0 + warp_m * 64 + (lane >> 2);
#pragma unroll
    for (int mt = 0; mt < 4; mt++) {
#pragma unroll
        for (int ng = 0; ng < 4; ng++) {
            int col = col0 + warp_n * 32 + ng * 8 + 2 * (lane & 3);
            float b0 = bias ? bias[col + 0] : 0.f;
            float b1 = bias ? bias[col + 1] : 0.f;
            float2 v0 = make_float2(acc[mt][ng][0] + b0, acc[mt][ng][1] + b1);
            float2 v1 = make_float2(acc[mt][ng][2] + b0, acc[mt][ng][3] + b1);
            *(float2*)(C + (size_t)(rowE + mt * 16) * Nn + col) = v0;
            *(float2*)(C + (size_t)(rowE + mt * 16 + 8) * Nn + col) = v1;
        }
    }
#undef ISSUE_CHUNK
}

// ---------------- Q = nq @ Wq + bq  (batch-invariant, tiny) ----------------
__global__ void q_kernel(const float* __restrict__ nq, const float* __restrict__ Wq,
                         const float* __restrict__ bq, float* __restrict__ Qout)
{
    int d = blockIdx.x * 128 + threadIdx.x;
    __shared__ float nqs[CK * 128];
    float acc[CK];
#pragma unroll
    for (int k = 0; k < CK; k++) acc[k] = bq[d];
    for (int e0 = 0; e0 < CDn; e0 += 128) {
        for (int idx = threadIdx.x; idx < CK * 128; idx += 128) {
            int k = idx >> 7, e = idx & 127;
            nqs[idx] = nq[k * CDn + e0 + e];
        }
        __syncthreads();
        for (int e = 0; e < 128; e++) {
            float wv = Wq[(size_t)(e0 + e) * CDn + d];
#pragma unroll
            for (int k = 0; k < CK; k++) acc[k] += nqs[k * 128 + e] * wv;
        }
        __syncthreads();
    }
#pragma unroll
    for (int k = 0; k < CK; k++) Qout[k * CDn + d] = acc[k];
}

// ---------------- scores + masked softmax over K -> S [B,N,K] --------------
__global__ void scores_kernel(const float* __restrict__ Kt, const float* __restrict__ Q,
                              const int* __restrict__ mask, float* __restrict__ S)
{
    int bn = blockIdx.x;
    __shared__ float kt[CDn];
    __shared__ float sk[CK];
    for (int i = threadIdx.x; i < CDn; i += 256)
        kt[i] = Kt[(size_t)bn * CDn + i];
    __syncthreads();
    int w = threadIdx.x >> 5, lane = threadIdx.x & 31;
    for (int k = w; k < CK; k += 8) {
        float acc = 0.f;
        for (int d = lane; d < CDn; d += 32)
            acc += Q[k * CDn + d] * kt[d];
#pragma unroll
        for (int off = 16; off; off >>= 1)
            acc += __shfl_xor_sync(0xffffffffu, acc, off);
        if (lane == 0) sk[k] = acc;
    }
    __syncthreads();
    if (threadIdx.x < 32) {
        int k = lane;
        if (mask[bn] == 0) {
            if (k < CK) S[(size_t)bn * CK + k] = 1.0f / CK;
        } else {
            const float scale = rsqrtf((float)(CDn / 8));
            float v = (k < CK) ? sk[k] * scale : -INFINITY;
            float m = v;
#pragma unroll
            for (int off = 16; off; off >>= 1)
                m = fmaxf(m, __shfl_xor_sync(0xffffffffu, m, off));
            float e = (k < CK) ? __expf(v - m) : 0.f;
            float s = e;
#pragma unroll
            for (int off = 16; off; off >>= 1)
                s += __shfl_xor_sync(0xffffffffu, s, off);
            if (k < CK) S[(size_t)bn * CK + k] = e / s;
        }
    }
}

// ------- V[b,k,d] = sum_n S[b,n,k]*Vt[b,n,d]; then gate-fuse with nq -------
__global__ void vagg_kernel(const float* __restrict__ S, const float* __restrict__ Vt,
                            const float* __restrict__ nq, const float* __restrict__ fg,
                            float* __restrict__ Vout)
{
    int b = blockIdx.y;
    int d0 = blockIdx.x * 128;
    __shared__ float Ss[CN * CK];
    __shared__ float vts[128];
    for (int i = threadIdx.x; i < CN * CK; i += 256)
        Ss[i] = S[(size_t)b * CN * CK + i];
    int k  = threadIdx.x >> 4;
    int ds = threadIdx.x & 15;
    float acc[8] = {};
    for (int n = 0; n < CN; n++) {
        __syncthreads();
        if (threadIdx.x < 128)
            vts[threadIdx.x] = Vt[((size_t)b * CN + n) * CDn + d0 + threadIdx.x];
        __syncthreads();
        float sv = Ss[n * CK + k];
#pragma unroll
        for (int c = 0; c < 8; c++) acc[c] += sv * vts[ds + 16 * c];
    }
    float g = 1.f / (1.f + __expf(-fg[0]));
#pragma unroll
    for (int c = 0; c < 8; c++) {
        int d = d0 + ds + 16 * c;
        Vout[((size_t)b * CK + k) * CDn + d] = (1.f - g) * acc[c] + g * nq[k * CDn + d];
    }
}

// ---------------- edge reduce: E[b,i,j] = sum_h relu(hi+hj+be1)*We2 + be2 ---
template <bool DO_SOFTMAX>
__global__ void edge_kernel(const float* __restrict__ Hi, const float* __restrict__ Hj,
                            const float* __restrict__ be1, const float* __restrict__ We2,
                            const float* __restrict__ be2, float* __restrict__ out)
{
    extern __shared__ float sm[];
    float* HIs  = sm;
    float* HJs  = HIs + CHID * CK;
    float* be1s = HJs + CHID * CK;
    float* we2s = be1s + CHID;
    float* Es   = we2s + CHID;
    int b = blockIdx.x;
    for (int idx = threadIdx.x; idx < CK * CHID; idx += 256) {
        int i = idx / CHID, h = idx % CHID;
        HIs[h * CK + i] = Hi[((size_t)b * CK + i) * CHID + h];
        HJs[h * CK + i] = Hj[((size_t)b * CK + i) * CHID + h];
    }
    for (int idx = threadIdx.x; idx < CHID; idx += 256) {
        be1s[idx] = be1[idx];
        we2s[idx] = We2[idx];
    }
    __syncthreads();
    int i = threadIdx.x >> 4, j = threadIdx.x & 15;
    float acc = be2[0];
#pragma unroll 4
    for (int h = 0; h < CHID; h++) {
        float v = HIs[h * CK + i] + HJs[h * CK + j] + be1s[h];
        acc += fmaxf(v, 0.f) * we2s[h];
    }
    if (!DO_SOFTMAX) {
        out[(size_t)b * CK * CK + i * CK + j] = acc;
    } else {
        Es[i * CK + j] = acc;
        __syncthreads();
        float m = -INFINITY;
#pragma unroll
        for (int jj = 0; jj < CK; jj++) m = fmaxf(m, Es[i * CK + jj]);
        float ssum = 0.f;
#pragma unroll
        for (int jj = 0; jj < CK; jj++) ssum += __expf(Es[i * CK + jj] - m);
        out[(size_t)b * CK * CK + i * CK + j] = __expf(acc - m) / ssum;
    }
}

// ---------------- GNN update: V[b,i,:] += relu(sum_j A[b,i,j]*M[b,j,:]) ----
__global__ void gnn_update(const float* __restrict__ A, const float* __restrict__ M,
                           float* __restrict__ V)
{
    int b = blockIdx.y;
    int d0 = blockIdx.x * 128;
    __shared__ float As[CK * CK];
    __shared__ float Ms[128];
    for (int idx = threadIdx.x; idx < CK * CK; idx += 256)
        As[idx] = A[(size_t)b * CK * CK + idx];
    int i  = threadIdx.x >> 4;
    int ds = threadIdx.x & 15;
    float acc[8] = {};
    for (int j = 0; j < CK; j++) {
        __syncthreads();
        if (threadIdx.x < 128)
            Ms[threadIdx.x] = M[((size_t)b * CK + j) * CDn + d0 + threadIdx.x];
        __syncthreads();
        float a = As[i * CK + j];
#pragma unroll
        for (int c = 0; c < 8; c++) acc[c] += a * Ms[ds + 16 * c];
    }
#pragma unroll
    for (int c = 0; c < 8; c++) {
        size_t o = ((size_t)b * CK + i) * CDn + d0 + ds + 16 * c;
        V[o] += fmaxf(acc[c], 0.f);
    }
}

// ---------------------------------------------------------------------------
extern "C" void kernel_launch(void* const* d_in, const int* in_sizes, int n_in,
                              void* d_out, int out_size)
{
    const float* w    = (const float*)d_in[0];
    const int*   mask = (const int*)  d_in[1];
    const float* nq   = (const float*)d_in[2];
    const float* Wq   = (const float*)d_in[3];
    const float* bq   = (const float*)d_in[4];
    const float* Wk   = (const float*)d_in[5];
    const float* bk   = (const float*)d_in[6];
    const float* Wv   = (const float*)d_in[7];
    const float* bv   = (const float*)d_in[8];
    const float* We1  = (const float*)d_in[9];
    const float* be1  = (const float*)d_in[10];
    const float* We2  = (const float*)d_in[11];
    const float* be2  = (const float*)d_in[12];
    const float* fg   = (const float*)d_in[13];
    const float* Wg   = (const float*)d_in[14];
    const float* bg   = (const float*)d_in[15];

    float* S = (float*)d_out;                       // [B,N,K]
    float* V = S + (size_t)CB * CN * CK;            // [B,K,Dn]
    float* E = V + (size_t)CB * CK * CDn;           // [B,K,K]

    float *Kt, *Vt, *Qb, *Ab, *Hi, *Hj, *Mg;
    __nv_bfloat16 *wh, *wl, *vh, *vl, *Wth, *Wtl;
    cudaGetSymbolAddress((void**)&Kt, g_Kt);
    cudaGetSymbolAddress((void**)&Vt, g_Vt);
    cudaGetSymbolAddress((void**)&Qb, g_Q);
    cudaGetSymbolAddress((void**)&Ab, g_A);
    cudaGetSymbolAddress((void**)&Hi, g_Hi);
    cudaGetSymbolAddress((void**)&Hj, g_Hj);
    cudaGetSymbolAddress((void**)&Mg, g_Mg);
    cudaGetSymbolAddress((void**)&wh, g_wh);
    cudaGetSymbolAddress((void**)&wl, g_wl);
    cudaGetSymbolAddress((void**)&vh, g_vh);
    cudaGetSymbolAddress((void**)&vl, g_vl);
    cudaGetSymbolAddress((void**)&Wth, g_Wth);
    cudaGetSymbolAddress((void**)&Wtl, g_Wtl);

    const int EDGE_SMEM = (2 * CHID * CK + 2 * CHID + CK * CK) * (int)sizeof(float);
    cudaFuncSetAttribute(edge_kernel<true>,  cudaFuncAttributeMaxDynamicSharedMemorySize, EDGE_SMEM);
    cudaFuncSetAttribute(edge_kernel<false>, cudaFuncAttributeMaxDynamicSharedMemorySize, EDGE_SMEM);
    cudaFuncSetAttribute(gemm_mma, cudaFuncAttributeMaxDynamicSharedMemorySize, GSMEM);

    const int Mtok = CB * CN;   // 19712
    const int Mkv  = CB * CK;   // 4096
    dim3 tb(32, 8);

    // 0. conversions: w -> bf16 hi/lo; weights -> transposed bf16 hi/lo
    split_rows<<<(Mtok * GK / 4 + 255) / 256, 256>>>(w, wh, wl, Mtok * GK / 4);
    split_transpose<<<dim3(768 / 32, GK / 32), tb>>>(Wk, 768, Wth, Wtl);
    split_transpose<<<dim3(768 / 32, GK / 32), tb>>>(Wv, 768, Wth + (size_t)768 * GK, Wtl + (size_t)768 * GK);
    split_transpose<<<dim3(512 / 32, GK / 32), tb>>>(We1, 512, Wth + (size_t)1536 * GK, Wtl + (size_t)1536 * GK);
    split_transpose<<<dim3(512 / 32, GK / 32), tb>>>(We1 + (size_t)768 * 512, 512,
                                                     Wth + (size_t)2048 * GK, Wtl + (size_t)2048 * GK);
    split_transpose<<<dim3(768 / 32, GK / 32), tb>>>(Wg, 768, Wth + (size_t)2560 * GK, Wtl + (size_t)2560 * GK);
    split_transpose<<<dim3(768 / 32, GK / 32), tb>>>(Wg + (size_t)768 * 768, 768,
                                                     Wth + (size_t)3328 * GK, Wtl + (size_t)3328 * GK);

    // 1. Q (batch-invariant, fp32)
    q_kernel<<<CDn / 128, 128>>>(nq, Wq, bq, Qb);

    // 2. Kt, Vt projections (mma.sync)
    gemm_mma<<<dim3(CDn / 128, Mtok / 128), 256, GSMEM>>>(wh, wl, Wth, Wtl, bk, Kt, CDn);
    gemm_mma<<<dim3(CDn / 128, Mtok / 128), 256, GSMEM>>>(wh, wl, Wth + (size_t)768 * GK,
                                                          Wtl + (size_t)768 * GK, bv, Vt, CDn);

    // 3. scores + masked softmax over K -> S
    scores_kernel<<<Mtok, 256>>>(Kt, Qb, mask, S);

    // 4. V aggregation + fuse gate
    vagg_kernel<<<dim3(CDn / 128, CB), 256>>>(S, Vt, nq, fg, V);
    split_rows<<<(Mkv * GK / 4 + 255) / 256, 256>>>(V, vh, vl, Mkv * GK / 4);

    // 5. pre-GNN edge logits -> A = softmax(E)
    gemm_mma<<<dim3(CHID / 128, Mkv / 128), 256, GSMEM>>>(vh, vl, Wth + (size_t)1536 * GK,
                                                          Wtl + (size_t)1536 * GK, nullptr, Hi, CHID);
    gemm_mma<<<dim3(CHID / 128, Mkv / 128), 256, GSMEM>>>(vh, vl, Wth + (size_t)2048 * GK,
                                                          Wtl + (size_t)2048 * GK, nullptr, Hj, CHID);
    edge_kernel<true><<<CB, 256, EDGE_SMEM>>>(Hi, Hj, be1, We2, be2, Ab);

    // 6. GNN layers
    for (int l = 0; l < CL; l++) {
        gemm_mma<<<dim3(CDn / 128, Mkv / 128), 256, GSMEM>>>(
            vh, vl, Wth + (size_t)(2560 + 768 * l) * GK, Wtl + (size_t)(2560 + 768 * l) * GK,
            bg + (size_t)l * CDn, Mg, CDn);
        gnn_update<<<dim3(CDn / 128, CB), 256>>>(Ab, Mg, V);
        split_rows<<<(Mkv * GK / 4 + 255) / 256, 256>>>(V, vh, vl, Mkv * GK / 4);
    }

    // 7. post-GNN edge logits -> E (output)
    gemm_mma<<<dim3(CHID / 128, Mkv / 128), 256, GSMEM>>>(vh, vl, Wth + (size_t)1536 * GK,
                                                          Wtl + (size_t)1536 * GK, nullptr, Hi, CHID);
    gemm_mma<<<dim3(CHID / 128, Mkv / 128), 256, GSMEM>>>(vh, vl, Wth + (size_t)2048 * GK,
                                                          Wtl + (size_t)2048 * GK, nullptr, Hj, CHID);
    edge_kernel<false><<<CB, 256, EDGE_SMEM>>>(Hi, Hj, be1, We2, be2, E);
}

// round 4
// speedup vs baseline: 2.4431x; 1.0949x over previous
#include <cuda_runtime.h>
#include <cuda_bf16.h>
#include <math.h>
#include <stdint.h>

#define CB   256   // batch
#define CN   77    // tokens
#define CD   768   // token dim
#define CK   16    // nodes
#define CDn  768   // node dim
#define CHID 512   // edge hidden
#define CL   2     // gnn layers

#define GK     768          // shared inner dim of all GEMMs
#define KCH    64           // bf16 K elems per chunk (128B rows)
#define NCHUNK (GK / KCH)   // 12
#define TILEB  16384        // one 128x64 bf16 tile in smem
#define BUFB   (4 * TILEB)  // Ah, Al, Bh, Bl
#define NSTAGE 3
#define GSMEM  (NSTAGE * BUFB)  // 196608

// ---------------- scratch (device globals; no allocation allowed) ----------
__device__ float g_Kt[CB * CN * CDn];
__device__ float g_Vt[CB * CN * CDn];
__device__ float g_Q [CK * CDn];
__device__ float g_Qp[8 * CK * CDn];
__device__ float g_A [CB * CK * CK];
__device__ float g_H [CB * CK * 2 * CHID];   // [4096, 1024]: Hi | Hj
__device__ float g_Mg[CB * CK * CDn];
__device__ __nv_bfloat16 g_wh[CB * CN * CDn];
__device__ __nv_bfloat16 g_wl[CB * CN * CDn];
__device__ __nv_bfloat16 g_vh[CB * CK * CDn];
__device__ __nv_bfloat16 g_vl[CB * CK * CDn];
// transposed weights [Nrows, 768]: Wk(0) Wv(768) We1a(1536) We1b(2048) Wg0(2560) Wg1(3328)
__device__ __nv_bfloat16 g_Wth[4096 * GK];
__device__ __nv_bfloat16 g_Wtl[4096 * GK];

// ---------------- PTX helpers ----------------------------------------------
__device__ __forceinline__ uint32_t smem_u32(const void* p) {
    uint32_t a;
    asm("{ .reg .u64 t; cvta.to.shared.u64 t, %1; cvt.u32.u64 %0, t; }" : "=r"(a) : "l"(p));
    return a;
}
__device__ __forceinline__ void cpa16(uint32_t sa, const void* ga) {
    asm volatile("cp.async.cg.shared.global [%0], [%1], 16;" :: "r"(sa), "l"(ga));
}
__device__ __forceinline__ void ldsm4(uint32_t* r, uint32_t addr) {
    asm volatile("ldmatrix.sync.aligned.m8n8.x4.shared.b16 {%0,%1,%2,%3}, [%4];"
                 : "=r"(r[0]), "=r"(r[1]), "=r"(r[2]), "=r"(r[3]) : "r"(addr));
}
__device__ __forceinline__ void mma16816(float* c, const uint32_t* a, uint32_t b0, uint32_t b1) {
    asm volatile(
        "mma.sync.aligned.m16n8k16.row.col.f32.bf16.bf16.f32 "
        "{%0,%1,%2,%3}, {%4,%5,%6,%7}, {%8,%9}, {%0,%1,%2,%3};"
        : "+f"(c[0]), "+f"(c[1]), "+f"(c[2]), "+f"(c[3])
        : "r"(a[0]), "r"(a[1]), "r"(a[2]), "r"(a[3]), "r"(b0), "r"(b1));
}
__device__ __forceinline__ void split_bf16(float x, __nv_bfloat16& h, __nv_bfloat16& l) {
    h = __float2bfloat16(x);
    l = __float2bfloat16(x - __bfloat162float(h));
}

// ---------------- split/convert kernels -------------------------------------
__global__ void split_rows(const float* __restrict__ x, __nv_bfloat16* __restrict__ hi,
                           __nv_bfloat16* __restrict__ lo, int n4) {
    int i = blockIdx.x * 256 + threadIdx.x;
    if (i >= n4) return;
    float4 v = ((const float4*)x)[i];
    __nv_bfloat16 h0, h1, h2, h3, l0, l1, l2, l3;
    split_bf16(v.x, h0, l0); split_bf16(v.y, h1, l1);
    split_bf16(v.z, h2, l2); split_bf16(v.w, h3, l3);
    ((__nv_bfloat162*)hi)[2 * i + 0] = __nv_bfloat162(h0, h1);
    ((__nv_bfloat162*)hi)[2 * i + 1] = __nv_bfloat162(h2, h3);
    ((__nv_bfloat162*)lo)[2 * i + 0] = __nv_bfloat162(l0, l1);
    ((__nv_bfloat162*)lo)[2 * i + 1] = __nv_bfloat162(l2, l3);
}

// all 6 weight matrices transposed+split in one launch; z selects the matrix
__global__ void split_weights(const float* __restrict__ Wk, const float* __restrict__ Wv,
                              const float* __restrict__ We1, const float* __restrict__ Wg,
                              __nv_bfloat16* __restrict__ dh, __nv_bfloat16* __restrict__ dl) {
    int z = blockIdx.z;
    const float* src; int ld, ncols, dsto;
    switch (z) {
        case 0: src = Wk;                        ld = 768; ncols = 768; dsto = 0;    break;
        case 1: src = Wv;                        ld = 768; ncols = 768; dsto = 768;  break;
        case 2: src = We1;                       ld = 512; ncols = 512; dsto = 1536; break;
        case 3: src = We1 + (size_t)768 * 512;   ld = 512; ncols = 512; dsto = 2048; break;
        case 4: src = Wg;                        ld = 768; ncols = 768; dsto = 2560; break;
        default: src = Wg + (size_t)768 * 768;   ld = 768; ncols = 768; dsto = 3328; break;
    }
    int n0 = blockIdx.x * 32, k0 = blockIdx.y * 32;
    if (n0 >= ncols) return;
    __shared__ float t[32][33];
    int tx = threadIdx.x, ty = threadIdx.y;
#pragma unroll
    for (int j = 0; j < 4; j++)
        t[ty + 8 * j][tx] = src[(size_t)(k0 + ty + 8 * j) * ld + n0 + tx];
    __syncthreads();
#pragma unroll
    for (int j = 0; j < 4; j++) {
        float x = t[tx][ty + 8 * j];
        __nv_bfloat16 h, l;
        split_bf16(x, h, l);
        size_t o = (size_t)(dsto + n0 + ty + 8 * j) * GK + k0 + tx;
        dh[o] = h;
        dl[o] = l;
    }
}

// ---------------- mma.sync split-bf16 GEMM, 3-stage cp.async pipeline --------
__global__ void __launch_bounds__(256, 1) gemm_mma(
    const __nv_bfloat16* __restrict__ Ah, const __nv_bfloat16* __restrict__ Al,
    const __nv_bfloat16* __restrict__ Bh, const __nv_bfloat16* __restrict__ Bl,
    const float* __restrict__ bias, float* __restrict__ C, int Nn)
{
    extern __shared__ char smem[];
    const uint32_t sbase = smem_u32(smem);
    const int tid = threadIdx.x;
    const int lane = tid & 31, wid = tid >> 5;
    const int warp_m = wid >> 2, warp_n = wid & 3;   // 2 x 4 warp grid
    const int row0 = blockIdx.y * 128;
    const int col0 = blockIdx.x * 128;

    float acc[4][4][4];
#pragma unroll
    for (int a = 0; a < 4; a++)
#pragma unroll
        for (int b = 0; b < 4; b++)
#pragma unroll
            for (int c = 0; c < 4; c++) acc[a][b][c] = 0.f;

#define ISSUE_CHUNK(chunk, buf)                                                     \
    do {                                                                            \
        uint32_t bufo_ = sbase + (buf) * BUFB;                                      \
        _Pragma("unroll")                                                           \
        for (int it = 0; it < 16; it++) {                                           \
            int idx_ = it * 256 + tid;                                              \
            int t_ = idx_ >> 10;                                                    \
            int r_ = (idx_ >> 3) & 127;                                             \
            int c_ = idx_ & 7;                                                      \
            const __nv_bfloat16* sp_ =                                              \
                (t_ == 0) ? Ah + (size_t)(row0 + r_) * GK :                         \
                (t_ == 1) ? Al + (size_t)(row0 + r_) * GK :                         \
                (t_ == 2) ? Bh + (size_t)(col0 + r_) * GK :                         \
                            Bl + (size_t)(col0 + r_) * GK;                          \
            sp_ += (chunk) * KCH + c_ * 8;                                          \
            uint32_t sa_ = bufo_ + t_ * TILEB + r_ * 128 + ((c_ ^ (r_ & 7)) << 4);  \
            cpa16(sa_, sp_);                                                        \
        }                                                                           \
        asm volatile("cp.async.commit_group;" ::: "memory");                        \
    } while (0)

    ISSUE_CHUNK(0, 0);
    ISSUE_CHUNK(1, 1);

    const int rA  = warp_m * 64 + (lane & 15);
    const int khA = lane >> 4;
    const int rB  = warp_n * 32 + (lane & 7) + ((lane >> 4) << 3);
    const int khB = (lane >> 3) & 1;
    const int swA = rA & 7, swB = rB & 7;

    for (int i = 0; i < NCHUNK; i++) {
        if (i + 2 < NCHUNK) {
            ISSUE_CHUNK(i + 2, (i + 2) % NSTAGE);
            asm volatile("cp.async.wait_group 2;" ::: "memory");
        } else if (i + 1 < NCHUNK) {
            asm volatile("cp.async.wait_group 1;" ::: "memory");
        } else {
            asm volatile("cp.async.wait_group 0;" ::: "memory");
        }
        __syncthreads();
        uint32_t bufo = sbase + (i % NSTAGE) * BUFB;
#pragma unroll
        for (int kk = 0; kk < 4; kk++) {
            uint32_t a[2][4][4];
            uint32_t b[2][2][4];
            int ckA = kk * 2 + khA;
            int ckB = kk * 2 + khB;
#pragma unroll
            for (int mt = 0; mt < 4; mt++) {
                uint32_t ad = bufo + (rA + mt * 16) * 128 + (((ckA ^ swA)) << 4);
                ldsm4(a[0][mt], ad);
                ldsm4(a[1][mt], ad + TILEB);
            }
#pragma unroll
            for (int nt = 0; nt < 2; nt++) {
                uint32_t bd = bufo + 2 * TILEB + (rB + nt * 16) * 128 + (((ckB ^ swB)) << 4);
                ldsm4(b[0][nt], bd);
                ldsm4(b[1][nt], bd + TILEB);
            }
#pragma unroll
            for (int mt = 0; mt < 4; mt++)
#pragma unroll
                for (int ng = 0; ng < 4; ng++) {
                    uint32_t b0h = b[0][ng >> 1][(ng & 1) * 2 + 0];
                    uint32_t b1h = b[0][ng >> 1][(ng & 1) * 2 + 1];
                    uint32_t b0l = b[1][ng >> 1][(ng & 1) * 2 + 0];
                    uint32_t b1l = b[1][ng >> 1][(ng & 1) * 2 + 1];
                    mma16816(acc[mt][ng], a[0][mt], b0h, b1h);   // Ah*Bh
                    mma16816(acc[mt][ng], a[0][mt], b0l, b1l);   // Ah*Bl
                    mma16816(acc[mt][ng], a[1][mt], b0h, b1h);   // Al*Bh
                }
        }
        __syncthreads();
    }

    const int rowE = row0 + warp_m * 64 + (lane >> 2);
#pragma unroll
    for (int mt = 0; mt < 4; mt++) {
#pragma unroll
        for (int ng = 0; ng < 4; ng++) {
            int col = col0 + warp_n * 32 + ng * 8 + 2 * (lane & 3);
            float b0 = bias ? bias[col + 0] : 0.f;
            float b1 = bias ? bias[col + 1] : 0.f;
            float2 v0 = make_float2(acc[mt][ng][0] + b0, acc[mt][ng][1] + b1);
            float2 v1 = make_float2(acc[mt][ng][2] + b0, acc[mt][ng][3] + b1);
            *(float2*)(C + (size_t)(rowE + mt * 16) * Nn + col) = v0;
            *(float2*)(C + (size_t)(rowE + mt * 16 + 8) * Nn + col) = v1;
        }
    }
#undef ISSUE_CHUNK
}

// ---------------- Q = nq @ Wq + bq: partial over e-ranges, then reduce -----
__global__ void q_partial(const float* __restrict__ nq, const float* __restrict__ Wq,
                          float* __restrict__ Qp)
{
    int d = blockIdx.x * 128 + threadIdx.x;
    int e0 = blockIdx.y * 96;
    float acc[CK] = {};
    for (int e = e0; e < e0 + 96; e++) {
        float wv = Wq[(size_t)e * CDn + d];
#pragma unroll
        for (int k = 0; k < CK; k++) acc[k] += nq[k * CDn + e] * wv;
    }
#pragma unroll
    for (int k = 0; k < CK; k++)
        Qp[((size_t)blockIdx.y * CK + k) * CDn + d] = acc[k];
}
__global__ void q_reduce(const float* __restrict__ Qp, const float* __restrict__ bq,
                         float* __restrict__ Qout)
{
    int i = blockIdx.x * 256 + threadIdx.x;  // i over 16*768
    if (i >= CK * CDn) return;
    float s = bq[i % CDn];
#pragma unroll
    for (int y = 0; y < 8; y++) s += Qp[(size_t)y * CK * CDn + i];
    Qout[i] = s;
}

// ------- scores + masked softmax, 16 tokens per block -----------------------
#define SC_SMEM ((CK * CDn + 16 * CDn + 16 * CK) * 4)
__global__ void scores16(const float* __restrict__ Kt, const float* __restrict__ Q,
                         const int* __restrict__ mask, float* __restrict__ S)
{
    extern __shared__ float sm[];
    float* Qs  = sm;                 // [16][768]
    float* kts = Qs + CK * CDn;      // [16 tokens][768]
    float* sk  = kts + 16 * CDn;     // [16 tokens][16 k]
    int t0 = blockIdx.x * 16;
    int tid = threadIdx.x, lane = tid & 31, w = tid >> 5;

    for (int i = tid; i < CK * CDn; i += 256) Qs[i] = Q[i];
    for (int i = tid; i < 16 * CDn; i += 256) kts[i] = Kt[(size_t)t0 * CDn + i];
    __syncthreads();

#pragma unroll
    for (int tt = 2 * w; tt < 2 * w + 2; tt++) {
        const float* kr = kts + tt * CDn;
#pragma unroll
        for (int k = 0; k < CK; k++) {
            float acc = 0.f;
#pragma unroll
            for (int j = 0; j < CDn / 32; j++)
                acc += Qs[k * CDn + j * 32 + lane] * kr[j * 32 + lane];
#pragma unroll
            for (int off = 16; off; off >>= 1)
                acc += __shfl_xor_sync(0xffffffffu, acc, off);
            if (lane == 0) sk[tt * CK + k] = acc;
        }
    }
    __syncthreads();

    int tt = tid >> 4, k = tid & 15;
    int bn = t0 + tt;
    if (mask[bn] == 0) {
        S[(size_t)bn * CK + k] = 1.0f / CK;
    } else {
        const float scale = rsqrtf((float)(CDn / 8));
        float m = -INFINITY, ssum = 0.f;
#pragma unroll
        for (int j = 0; j < CK; j++) m = fmaxf(m, sk[tt * CK + j]);
#pragma unroll
        for (int j = 0; j < CK; j++) ssum += __expf((sk[tt * CK + j] - m) * scale);
        S[(size_t)bn * CK + k] = __expf((sk[tt * CK + k] - m) * scale) / ssum;
    }
}

// ------- V agg + fuse gate + bf16 split --------------------------------------
__global__ void vagg_kernel(const float* __restrict__ S, const float* __restrict__ Vt,
                            const float* __restrict__ nq, const float* __restrict__ fg,
                            float* __restrict__ Vout,
                            __nv_bfloat16* __restrict__ vh, __nv_bfloat16* __restrict__ vl)
{
    int b = blockIdx.y;
    int d0 = blockIdx.x * 128;
    __shared__ float Ss[CN * CK];
    __shared__ float vts[128];
    for (int i = threadIdx.x; i < CN * CK; i += 256)
        Ss[i] = S[(size_t)b * CN * CK + i];
    int k  = threadIdx.x >> 4;
    int ds = threadIdx.x & 15;
    float acc[8] = {};
    for (int n = 0; n < CN; n++) {
        __syncthreads();
        if (threadIdx.x < 128)
            vts[threadIdx.x] = Vt[((size_t)b * CN + n) * CDn + d0 + threadIdx.x];
        __syncthreads();
        float sv = Ss[n * CK + k];
#pragma unroll
        for (int c = 0; c < 8; c++) acc[c] += sv * vts[ds + 16 * c];
    }
    float g = 1.f / (1.f + __expf(-fg[0]));
#pragma unroll
    for (int c = 0; c < 8; c++) {
        int d = d0 + ds + 16 * c;
        size_t o = ((size_t)b * CK + k) * CDn + d;
        float v = (1.f - g) * acc[c] + g * nq[k * CDn + d];
        Vout[o] = v;
        __nv_bfloat16 h, l;
        split_bf16(v, h, l);
        vh[o] = h; vl[o] = l;
    }
}

// ---------------- edge reduce on merged H [4096, 1024] ----------------------
#define LDH (2 * CHID)
template <bool DO_SOFTMAX>
__global__ void edge_kernel(const float* __restrict__ H,
                            const float* __restrict__ be1, const float* __restrict__ We2,
                            const float* __restrict__ be2, float* __restrict__ out)
{
    extern __shared__ float sm[];
    float* HIs  = sm;
    float* HJs  = HIs + CHID * CK;
    float* be1s = HJs + CHID * CK;
    float* we2s = be1s + CHID;
    float* Es   = we2s + CHID;
    int b = blockIdx.x;
    for (int idx = threadIdx.x; idx < CK * CHID; idx += 256) {
        int i = idx / CHID, h = idx % CHID;
        HIs[h * CK + i] = H[((size_t)b * CK + i) * LDH + h];
        HJs[h * CK + i] = H[((size_t)b * CK + i) * LDH + CHID + h];
    }
    for (int idx = threadIdx.x; idx < CHID; idx += 256) {
        be1s[idx] = be1[idx];
        we2s[idx] = We2[idx];
    }
    __syncthreads();
    int i = threadIdx.x >> 4, j = threadIdx.x & 15;
    float acc = be2[0];
#pragma unroll 4
    for (int h = 0; h < CHID; h++) {
        float v = HIs[h * CK + i] + HJs[h * CK + j] + be1s[h];
        acc += fmaxf(v, 0.f) * we2s[h];
    }
    if (!DO_SOFTMAX) {
        out[(size_t)b * CK * CK + i * CK + j] = acc;
    } else {
        Es[i * CK + j] = acc;
        __syncthreads();
        float m = -INFINITY;
#pragma unroll
        for (int jj = 0; jj < CK; jj++) m = fmaxf(m, Es[i * CK + jj]);
        float ssum = 0.f;
#pragma unroll
        for (int jj = 0; jj < CK; jj++) ssum += __expf(Es[i * CK + jj] - m);
        out[(size_t)b * CK * CK + i * CK + j] = __expf(acc - m) / ssum;
    }
}

// ------- GNN update + bf16 split ---------------------------------------------
__global__ void gnn_update(const float* __restrict__ A, const float* __restrict__ M,
                           float* __restrict__ V,
                           __nv_bfloat16* __restrict__ vh, __nv_bfloat16* __restrict__ vl)
{
    int b = blockIdx.y;
    int d0 = blockIdx.x * 128;
    __shared__ float As[CK * CK];
    __shared__ float Ms[128];
    for (int idx = threadIdx.x; idx < CK * CK; idx += 256)
        As[idx] = A[(size_t)b * CK * CK + idx];
    int i  = threadIdx.x >> 4;
    int ds = threadIdx.x & 15;
    float acc[8] = {};
    for (int j = 0; j < CK; j++) {
        __syncthreads();
        if (threadIdx.x < 128)
            Ms[threadIdx.x] = M[((size_t)b * CK + j) * CDn + d0 + threadIdx.x];
        __syncthreads();
        float a = As[i * CK + j];
#pragma unroll
        for (int c = 0; c < 8; c++) acc[c] += a * Ms[ds + 16 * c];
    }
#pragma unroll
    for (int c = 0; c < 8; c++) {
        size_t o = ((size_t)b * CK + i) * CDn + d0 + ds + 16 * c;
        float v = V[o] + fmaxf(acc[c], 0.f);
        V[o] = v;
        __nv_bfloat16 h, l;
        split_bf16(v, h, l);
        vh[o] = h; vl[o] = l;
    }
}

// ---------------------------------------------------------------------------
extern "C" void kernel_launch(void* const* d_in, const int* in_sizes, int n_in,
                              void* d_out, int out_size)
{
    const float* w    = (const float*)d_in[0];
    const int*   mask = (const int*)  d_in[1];
    const float* nq   = (const float*)d_in[2];
    const float* Wq   = (const float*)d_in[3];
    const float* bq   = (const float*)d_in[4];
    const float* Wk   = (const float*)d_in[5];
    const float* bk   = (const float*)d_in[6];
    const float* Wv   = (const float*)d_in[7];
    const float* bv   = (const float*)d_in[8];
    const float* We1  = (const float*)d_in[9];
    const float* be1  = (const float*)d_in[10];
    const float* We2  = (const float*)d_in[11];
    const float* be2  = (const float*)d_in[12];
    const float* fg   = (const float*)d_in[13];
    const float* Wg   = (const float*)d_in[14];
    const float* bg   = (const float*)d_in[15];

    float* S = (float*)d_out;                       // [B,N,K]
    float* V = S + (size_t)CB * CN * CK;            // [B,K,Dn]
    float* E = V + (size_t)CB * CK * CDn;           // [B,K,K]

    float *Kt, *Vt, *Qb, *Qp, *Ab, *Hb, *Mg;
    __nv_bfloat16 *wh, *wl, *vh, *vl, *Wth, *Wtl;
    cudaGetSymbolAddress((void**)&Kt, g_Kt);
    cudaGetSymbolAddress((void**)&Vt, g_Vt);
    cudaGetSymbolAddress((void**)&Qb, g_Q);
    cudaGetSymbolAddress((void**)&Qp, g_Qp);
    cudaGetSymbolAddress((void**)&Ab, g_A);
    cudaGetSymbolAddress((void**)&Hb, g_H);
    cudaGetSymbolAddress((void**)&Mg, g_Mg);
    cudaGetSymbolAddress((void**)&wh, g_wh);
    cudaGetSymbolAddress((void**)&wl, g_wl);
    cudaGetSymbolAddress((void**)&vh, g_vh);
    cudaGetSymbolAddress((void**)&vl, g_vl);
    cudaGetSymbolAddress((void**)&Wth, g_Wth);
    cudaGetSymbolAddress((void**)&Wtl, g_Wtl);

    const int EDGE_SMEM = (2 * CHID * CK + 2 * CHID + CK * CK) * (int)sizeof(float);
    cudaFuncSetAttribute(edge_kernel<true>,  cudaFuncAttributeMaxDynamicSharedMemorySize, EDGE_SMEM);
    cudaFuncSetAttribute(edge_kernel<false>, cudaFuncAttributeMaxDynamicSharedMemorySize, EDGE_SMEM);
    cudaFuncSetAttribute(gemm_mma, cudaFuncAttributeMaxDynamicSharedMemorySize, GSMEM);
    cudaFuncSetAttribute(scores16, cudaFuncAttributeMaxDynamicSharedMemorySize, SC_SMEM);

    const int Mtok = CB * CN;   // 19712
    const int Mkv  = CB * CK;   // 4096
    dim3 tb(32, 8);

    // 1. w -> bf16 hi/lo
    split_rows<<<(Mtok * GK / 4 + 255) / 256, 256>>>(w, wh, wl, Mtok * GK / 4);
    // 2. all weights -> transposed bf16 hi/lo (one launch)
    split_weights<<<dim3(24, 24, 6), tb>>>(Wk, Wv, We1, Wg, Wth, Wtl);
    // 3-4. Q (batch-invariant)
    q_partial<<<dim3(CDn / 128, 8), 128>>>(nq, Wq, Qp);
    q_reduce<<<(CK * CDn + 255) / 256, 256>>>(Qp, bq, Qb);

    // 5-6. Kt, Vt projections (launch #6 = Vt gemm, profiled by ncu -s 5 -c 1)
    gemm_mma<<<dim3(CDn / 128, Mtok / 128), 256, GSMEM>>>(wh, wl, Wth, Wtl, bk, Kt, CDn);
    gemm_mma<<<dim3(CDn / 128, Mtok / 128), 256, GSMEM>>>(wh, wl, Wth + (size_t)768 * GK,
                                                          Wtl + (size_t)768 * GK, bv, Vt, CDn);

    // 7. scores + masked softmax
    scores16<<<Mtok / 16, 256, SC_SMEM>>>(Kt, Qb, mask, S);

    // 8. V aggregation + gate + split
    vagg_kernel<<<dim3(CDn / 128, CB), 256>>>(S, Vt, nq, fg, V, vh, vl);

    // 9-10. pre-GNN edge logits (merged Hi|Hj GEMM) -> A = softmax(E)
    gemm_mma<<<dim3(2 * CHID / 128, Mkv / 128), 256, GSMEM>>>(vh, vl, Wth + (size_t)1536 * GK,
                                                              Wtl + (size_t)1536 * GK, nullptr, Hb, LDH);
    edge_kernel<true><<<CB, 256, EDGE_SMEM>>>(Hb, be1, We2, be2, Ab);

    // 11-14. GNN layers
    for (int l = 0; l < CL; l++) {
        gemm_mma<<<dim3(CDn / 128, Mkv / 128), 256, GSMEM>>>(
            vh, vl, Wth + (size_t)(2560 + 768 * l) * GK, Wtl + (size_t)(2560 + 768 * l) * GK,
            bg + (size_t)l * CDn, Mg, CDn);
        gnn_update<<<dim3(CDn / 128, CB), 256>>>(Ab, Mg, V, vh, vl);
    }

    // 15-16. post-GNN edge logits -> E (output)
    gemm_mma<<<dim3(2 * CHID / 128, Mkv / 128), 256, GSMEM>>>(vh, vl, Wth + (size_t)1536 * GK,
                                                              Wtl + (size_t)1536 * GK, nullptr, Hb, LDH);
    edge_kernel<false><<<CB, 256, EDGE_SMEM>>>(Hb, be1, We2, be2, E);
}